// round 10
// baseline (speedup 1.0000x reference)
#include <cuda_runtime.h>
#include <cuda_bf16.h>
#include <cub/cub.cuh>
#include <cstdint>

// ---------------------------------------------------------------------------
// BaseLayerGate: affin = F[65536,1024] @ Wg[64,1024]^T ; greedy balanced
// assignment; outputs sbe[65536], splits[64]=1024 (x2), probs[65536]=1.0.
//
// Key: (63-e)<<48 | sortable(score)<<16 | token. ONE global descending radix
// sort over bits [16,54). Stability => ascending-token ties (jax top_k).
// ---------------------------------------------------------------------------

static constexpr int N_TOK = 65536;
static constexpr int D     = 1024;
static constexpr int E     = 64;
static constexpr int C     = N_TOK / E;   // 1024
static constexpr int TOTAL = N_TOK * E;   // 4M

__device__ unsigned long long g_keys_a[TOTAL];    // 32 MB
__device__ unsigned long long g_keys_b[TOTAL];    // 32 MB
__device__ int                g_offsets[E + 1];
__device__ unsigned char      g_temp[8u << 20];   // 8 MB CUB temp

__device__ __forceinline__ unsigned sortable_u(unsigned u) {
    return u ^ ((u & 0x80000000u) ? 0xFFFFFFFFu : 0x80000000u);
}
__device__ __forceinline__ unsigned long long ffma2(
    unsigned long long a, unsigned long long b, unsigned long long c) {
    unsigned long long d;
    asm("fma.rn.f32x2 %0, %1, %2, %3;" : "=l"(d) : "l"(a), "l"(b), "l"(c));
    return d;
}

// ---------------------------------------------------------------------------
// GEMM: 128 tokens x 64 experts per block, f32x2 dual-pumped FFMA.
// As stored PRE-DUPLICATED as float2{v,v}: one LDS.64 replaces LDS+MOV,
// cutting per-kk issue slots 34 -> 26 (< 32-cycle FFMA2 pipe floor).
// Identical values & ascending-k chain per accumulator half => bit-exact.
// ---------------------------------------------------------------------------
__global__ __launch_bounds__(256) void gemm_affin(
    const float* __restrict__ F, const float* __restrict__ W,
    unsigned long long* __restrict__ keys, int* __restrict__ offsets)
{
    __shared__ float2 Asd[128][33];   // duplicated feature values
    __shared__ float  Wst[32][66];    // [kk][expert]
    const int tid  = threadIdx.x;
    const int tile = blockIdx.x * 128;
    const int tx   = tid & 15;
    const int ty   = tid >> 4;

    if (blockIdx.x == 0 && tid <= E) offsets[tid] = tid * N_TOK;

    unsigned long long accp[8][2];
    #pragma unroll
    for (int i = 0; i < 8; ++i) { accp[i][0] = 0ull; accp[i][1] = 0ull; }

    for (int k0 = 0; k0 < D; k0 += 32) {
        #pragma unroll
        for (int it = 0; it < 4; ++it) {
            int idx = tid + it * 256;
            int row = idx >> 3, c4 = idx & 7;
            float4 v = *(const float4*)(F + (size_t)(tile + row) * D + k0 + c4 * 4);
            Asd[row][c4 * 4 + 0] = make_float2(v.x, v.x);
            Asd[row][c4 * 4 + 1] = make_float2(v.y, v.y);
            Asd[row][c4 * 4 + 2] = make_float2(v.z, v.z);
            Asd[row][c4 * 4 + 3] = make_float2(v.w, v.w);
        }
        #pragma unroll
        for (int it = 0; it < 2; ++it) {
            int idx = tid + it * 256;
            int row = idx >> 3, c4 = idx & 7;   // row = expert
            float4 v = *(const float4*)(W + (size_t)row * D + k0 + c4 * 4);
            Wst[c4 * 4 + 0][row] = v.x; Wst[c4 * 4 + 1][row] = v.y;
            Wst[c4 * 4 + 2][row] = v.z; Wst[c4 * 4 + 3][row] = v.w;
        }
        __syncthreads();
        #pragma unroll
        for (int kk = 0; kk < 32; ++kk) {
            unsigned long long wp0 = *(const unsigned long long*)&Wst[kk][tx * 4];
            unsigned long long wp1 = *(const unsigned long long*)&Wst[kk][tx * 4 + 2];
            #pragma unroll
            for (int i = 0; i < 8; ++i) {
                unsigned long long fp =
                    *(const unsigned long long*)&Asd[ty * 8 + i][kk];
                accp[i][0] = ffma2(fp, wp0, accp[i][0]);
                accp[i][1] = ffma2(fp, wp1, accp[i][1]);
            }
        }
        __syncthreads();
    }
    #pragma unroll
    for (int i = 0; i < 8; ++i) {
        unsigned t = (unsigned)(tile + ty * 8 + i);
        #pragma unroll
        for (int jp = 0; jp < 2; ++jp) {
            unsigned lo, hi;
            asm("mov.b64 {%0, %1}, %2;" : "=r"(lo), "=r"(hi) : "l"(accp[i][jp]));
            int e0 = tx * 4 + 2 * jp;
            unsigned long long k0 =
                ((unsigned long long)(63 - e0) << 48) |
                ((unsigned long long)sortable_u(lo) << 16) | t;
            unsigned long long k1 =
                ((unsigned long long)(63 - (e0 + 1)) << 48) |
                ((unsigned long long)sortable_u(hi) << 16) | t;
            keys[(size_t)e0 * N_TOK + t]       = k0;
            keys[(size_t)(e0 + 1) * N_TOK + t] = k1;
        }
    }
}

// ---------------------------------------------------------------------------
// Greedy: single CTA, 1024 threads x 4 tokens (4096/window) — the exact R6
// geometry that measured 669us (R7/R9 prefetch variants regressed: wasted
// cross-expert prefetch + register spills). Writes float(token) directly to
// d_out and also fills the constant tail (splits + ones) at startup.
// ---------------------------------------------------------------------------
__global__ __launch_bounds__(1024) void greedy_select(
    const unsigned long long* __restrict__ keys, float* __restrict__ out,
    int out_size)
{
    __shared__ unsigned mask[N_TOK / 32];  // 8 KB
    __shared__ int warp_sums[32];
    const int tid  = threadIdx.x;
    const int lane = tid & 31;
    const int wid  = tid >> 5;

    // fused tail fill: out[N_TOK..N_TOK+128) = 1024, rest = 1.0
    for (int i = N_TOK + tid; i < out_size; i += 1024)
        out[i] = (i < N_TOK + 2 * E) ? (float)C : 1.0f;

    for (int i = tid; i < N_TOK / 32; i += 1024) mask[i] = 0u;
    __syncthreads();

    for (int e = 0; e < E; ++e) {
        const unsigned long long* ord = keys + (size_t)e * N_TOK;
        int count = 0, pos = 0;
        while (count < C && pos < N_TOK) {
            ulonglong2 a = *(const ulonglong2*)(ord + pos + tid * 4);
            ulonglong2 b = *(const ulonglong2*)(ord + pos + tid * 4 + 2);
            unsigned tk[4];
            tk[0] = (unsigned)a.x & 0xFFFFu;
            tk[1] = (unsigned)a.y & 0xFFFFu;
            tk[2] = (unsigned)b.x & 0xFFFFu;
            tk[3] = (unsigned)b.y & 0xFFFFu;
            int fl[4], cnt = 0;
            #pragma unroll
            for (int j = 0; j < 4; ++j) {
                fl[j] = 1 - (int)((mask[tk[j] >> 5] >> (tk[j] & 31)) & 1u);
                cnt += fl[j];
            }
            int inc = cnt;
            #pragma unroll
            for (int off = 1; off < 32; off <<= 1) {
                int n = __shfl_up_sync(0xffffffffu, inc, off);
                if (lane >= off) inc += n;
            }
            if (lane == 31) warp_sums[wid] = inc;
            int thr_excl = inc - cnt;
            __syncthreads();
            if (wid == 0) {
                int v = warp_sums[lane];
                #pragma unroll
                for (int off = 1; off < 32; off <<= 1) {
                    int n = __shfl_up_sync(0xffffffffu, v, off);
                    if (lane >= off) v += n;
                }
                warp_sums[lane] = v;
            }
            __syncthreads();
            int warp_excl = wid ? warp_sums[wid - 1] : 0;
            int total     = warp_sums[31];
            int remaining = C - count;
            int r = warp_excl + thr_excl;
            #pragma unroll
            for (int j = 0; j < 4; ++j) {
                if (fl[j]) {
                    if (r < remaining) {
                        out[e * C + count + r] = (float)tk[j];
                        atomicOr(&mask[tk[j] >> 5], 1u << (tk[j] & 31));
                    }
                    ++r;
                }
            }
            count += min(total, remaining);
            pos += 4096;
            __syncthreads();
        }
    }
}

// ---------------------------------------------------------------------------
__global__ void pack_ones(float* __restrict__ out, int n)
{
    int i = blockIdx.x * blockDim.x + threadIdx.x;
    if (i < n) out[i] = 1.0f;
}

__global__ void pack_splits(float* __restrict__ out, int n)
{
    int i = blockIdx.x * blockDim.x + threadIdx.x;
    if (i < n) out[i] = (float)C;
}

// ---------------------------------------------------------------------------
extern "C" void kernel_launch(void* const* d_in, const int* in_sizes, int n_in,
                              void* d_out, int out_size)
{
    const float* F  = (const float*)d_in[0];
    const float* Wg = (const float*)d_in[1];
    if (n_in >= 2 && in_sizes[0] < in_sizes[1]) {
        F  = (const float*)d_in[1];
        Wg = (const float*)d_in[0];
    }

    unsigned long long* keys_a = nullptr;
    unsigned long long* keys_b = nullptr;
    int* offsets = nullptr;
    unsigned char* temp = nullptr;
    cudaGetSymbolAddress((void**)&keys_a,  g_keys_a);
    cudaGetSymbolAddress((void**)&keys_b,  g_keys_b);
    cudaGetSymbolAddress((void**)&offsets, g_offsets);
    cudaGetSymbolAddress((void**)&temp,    g_temp);

    if (out_size == N_TOK) {
        pack_ones<<<(N_TOK + 255) / 256, 256>>>((float*)d_out, N_TOK);
        return;
    }
    if (out_size == 2 * E || out_size == E) {
        pack_splits<<<1, 256>>>((float*)d_out, out_size);
        return;
    }

    gemm_affin<<<N_TOK / 128, 256>>>(F, Wg, keys_a, offsets);

    cub::DoubleBuffer<unsigned long long> dbuf(keys_a, keys_b);
    size_t temp_bytes = 0;
    cub::DeviceRadixSort::SortKeysDescending(
        nullptr, temp_bytes, dbuf, TOTAL, 16, 54);
    if (temp_bytes <= (size_t)(8u << 20)) {
        cub::DeviceRadixSort::SortKeysDescending(
            (void*)temp, temp_bytes, dbuf, TOTAL, 16, 54);
    } else {
        size_t tb2 = 0;
        cub::DeviceSegmentedRadixSort::SortKeysDescending(
            nullptr, tb2, dbuf, TOTAL, E, offsets, offsets + 1, 16, 48);
        if (tb2 > (size_t)(8u << 20)) tb2 = (size_t)(8u << 20);
        cub::DeviceSegmentedRadixSort::SortKeysDescending(
            (void*)temp, tb2, dbuf, TOTAL, E, offsets, offsets + 1, 16, 48);
    }

    greedy_select<<<1, 1024>>>(dbuf.Current(), (float*)d_out, out_size);
}

// round 11
// speedup vs baseline: 1.1244x; 1.1244x over previous
#include <cuda_runtime.h>
#include <cuda_bf16.h>
#include <cub/cub.cuh>
#include <cstdint>

// ---------------------------------------------------------------------------
// BaseLayerGate: affin = F[65536,1024] @ Wg[64,1024]^T ; greedy balanced
// assignment; outputs sbe[65536], splits[64]=1024 (x2), probs[65536]=1.0.
//
// Key: (63-e)<<48 | sortable(score)<<16 | token. ONE global descending radix
// sort over bits [16,54). Stability => ascending-token ties (jax top_k).
// ---------------------------------------------------------------------------

static constexpr int N_TOK = 65536;
static constexpr int D     = 1024;
static constexpr int E     = 64;
static constexpr int C     = N_TOK / E;   // 1024
static constexpr int TOTAL = N_TOK * E;   // 4M

__device__ unsigned long long g_keys_a[TOTAL];    // 32 MB
__device__ unsigned long long g_keys_b[TOTAL];    // 32 MB
__device__ int                g_offsets[E + 1];
__device__ unsigned char      g_temp[8u << 20];   // 8 MB CUB temp

__device__ __forceinline__ unsigned sortable_u(unsigned u) {
    return u ^ ((u & 0x80000000u) ? 0xFFFFFFFFu : 0x80000000u);
}
__device__ __forceinline__ unsigned long long ffma2(
    unsigned long long a, unsigned long long b, unsigned long long c) {
    unsigned long long d;
    asm("fma.rn.f32x2 %0, %1, %2, %3;" : "=l"(d) : "l"(a), "l"(b), "l"(c));
    return d;
}
__device__ __forceinline__ unsigned long long bcast2(float f) {
    unsigned long long p;
    asm("mov.b64 %0, {%1, %1};" : "=l"(p) : "f"(f));
    return p;
}

// ---------------------------------------------------------------------------
// GEMM: exact R6 configuration (measured 669us total; R10's duplicated-As
// variant cut occupancy 8->5 CTAs/SM and regressed +90us). 25.3KB smem,
// f32x2 dual-pumped FFMA, bit-exact ascending-k chain per accumulator half.
// ---------------------------------------------------------------------------
__global__ __launch_bounds__(256) void gemm_affin(
    const float* __restrict__ F, const float* __restrict__ W,
    unsigned long long* __restrict__ keys, int* __restrict__ offsets)
{
    __shared__ float As[128][33];
    __shared__ float Wst[32][66];   // [kk][expert]
    const int tid  = threadIdx.x;
    const int tile = blockIdx.x * 128;
    const int tx   = tid & 15;
    const int ty   = tid >> 4;

    if (blockIdx.x == 0 && tid <= E) offsets[tid] = tid * N_TOK;

    unsigned long long accp[8][2];
    #pragma unroll
    for (int i = 0; i < 8; ++i) { accp[i][0] = 0ull; accp[i][1] = 0ull; }

    for (int k0 = 0; k0 < D; k0 += 32) {
        #pragma unroll
        for (int it = 0; it < 4; ++it) {
            int idx = tid + it * 256;
            int row = idx >> 3, c4 = idx & 7;
            float4 v = *(const float4*)(F + (size_t)(tile + row) * D + k0 + c4 * 4);
            As[row][c4 * 4 + 0] = v.x; As[row][c4 * 4 + 1] = v.y;
            As[row][c4 * 4 + 2] = v.z; As[row][c4 * 4 + 3] = v.w;
        }
        #pragma unroll
        for (int it = 0; it < 2; ++it) {
            int idx = tid + it * 256;
            int row = idx >> 3, c4 = idx & 7;   // row = expert
            float4 v = *(const float4*)(W + (size_t)row * D + k0 + c4 * 4);
            Wst[c4 * 4 + 0][row] = v.x; Wst[c4 * 4 + 1][row] = v.y;
            Wst[c4 * 4 + 2][row] = v.z; Wst[c4 * 4 + 3][row] = v.w;
        }
        __syncthreads();
        #pragma unroll
        for (int kk = 0; kk < 32; ++kk) {
            unsigned long long wp0 = *(const unsigned long long*)&Wst[kk][tx * 4];
            unsigned long long wp1 = *(const unsigned long long*)&Wst[kk][tx * 4 + 2];
            #pragma unroll
            for (int i = 0; i < 8; ++i) {
                unsigned long long fp = bcast2(As[ty * 8 + i][kk]);
                accp[i][0] = ffma2(fp, wp0, accp[i][0]);
                accp[i][1] = ffma2(fp, wp1, accp[i][1]);
            }
        }
        __syncthreads();
    }
    #pragma unroll
    for (int i = 0; i < 8; ++i) {
        unsigned t = (unsigned)(tile + ty * 8 + i);
        #pragma unroll
        for (int jp = 0; jp < 2; ++jp) {
            unsigned lo, hi;
            asm("mov.b64 {%0, %1}, %2;" : "=r"(lo), "=r"(hi) : "l"(accp[i][jp]));
            int e0 = tx * 4 + 2 * jp;
            unsigned long long k0 =
                ((unsigned long long)(63 - e0) << 48) |
                ((unsigned long long)sortable_u(lo) << 16) | t;
            unsigned long long k1 =
                ((unsigned long long)(63 - (e0 + 1)) << 48) |
                ((unsigned long long)sortable_u(hi) << 16) | t;
            keys[(size_t)e0 * N_TOK + t]       = k0;
            keys[(size_t)(e0 + 1) * N_TOK + t] = k1;
        }
    }
}

// ---------------------------------------------------------------------------
// Greedy: R6 geometry (1024 threads x 4 tokens, no prefetch) with a leaner
// scan: after warp sums land in shared, EVERY warp redundantly shuffle-scans
// the 32-entry array -> 2 barriers/window instead of 3, no serialized warp-0
// phase. Allocation order unchanged (rank-stable). Writes float(token)
// directly to d_out; fills the constant tail at startup.
// ---------------------------------------------------------------------------
__global__ __launch_bounds__(1024) void greedy_select(
    const unsigned long long* __restrict__ keys, float* __restrict__ out,
    int out_size)
{
    __shared__ unsigned mask[N_TOK / 32];  // 8 KB
    __shared__ int warp_sums[32];
    const int tid  = threadIdx.x;
    const int lane = tid & 31;
    const int wid  = tid >> 5;

    // fused tail fill: out[N_TOK..N_TOK+128) = 1024, rest = 1.0
    for (int i = N_TOK + tid; i < out_size; i += 1024)
        out[i] = (i < N_TOK + 2 * E) ? (float)C : 1.0f;

    for (int i = tid; i < N_TOK / 32; i += 1024) mask[i] = 0u;
    __syncthreads();

    for (int e = 0; e < E; ++e) {
        const unsigned long long* ord = keys + (size_t)e * N_TOK;
        int count = 0, pos = 0;
        while (count < C && pos < N_TOK) {
            ulonglong2 a = *(const ulonglong2*)(ord + pos + tid * 4);
            ulonglong2 b = *(const ulonglong2*)(ord + pos + tid * 4 + 2);
            unsigned tk[4];
            tk[0] = (unsigned)a.x & 0xFFFFu;
            tk[1] = (unsigned)a.y & 0xFFFFu;
            tk[2] = (unsigned)b.x & 0xFFFFu;
            tk[3] = (unsigned)b.y & 0xFFFFu;
            int fl[4], cnt = 0;
            #pragma unroll
            for (int j = 0; j < 4; ++j) {
                fl[j] = 1 - (int)((mask[tk[j] >> 5] >> (tk[j] & 31)) & 1u);
                cnt += fl[j];
            }
            // intra-warp inclusive scan of per-thread counts
            int inc = cnt;
            #pragma unroll
            for (int off = 1; off < 32; off <<= 1) {
                int n = __shfl_up_sync(0xffffffffu, inc, off);
                if (lane >= off) inc += n;
            }
            if (lane == 31) warp_sums[wid] = inc;
            int thr_excl = inc - cnt;
            __syncthreads();
            // every warp redundantly scans the 32 warp sums (no 2nd barrier)
            int v = warp_sums[lane];
            #pragma unroll
            for (int off = 1; off < 32; off <<= 1) {
                int n = __shfl_up_sync(0xffffffffu, v, off);
                if (lane >= off) v += n;
            }
            int total     = __shfl_sync(0xffffffffu, v, 31);
            int warp_excl = wid ? __shfl_sync(0xffffffffu, v, wid - 1) : 0;
            int remaining = C - count;
            int r = warp_excl + thr_excl;
            #pragma unroll
            for (int j = 0; j < 4; ++j) {
                if (fl[j]) {
                    if (r < remaining) {
                        out[e * C + count + r] = (float)tk[j];
                        atomicOr(&mask[tk[j] >> 5], 1u << (tk[j] & 31));
                    }
                    ++r;
                }
            }
            count += min(total, remaining);
            pos += 4096;
            __syncthreads();
        }
    }
}

// ---------------------------------------------------------------------------
__global__ void pack_ones(float* __restrict__ out, int n)
{
    int i = blockIdx.x * blockDim.x + threadIdx.x;
    if (i < n) out[i] = 1.0f;
}

__global__ void pack_splits(float* __restrict__ out, int n)
{
    int i = blockIdx.x * blockDim.x + threadIdx.x;
    if (i < n) out[i] = (float)C;
}

// ---------------------------------------------------------------------------
extern "C" void kernel_launch(void* const* d_in, const int* in_sizes, int n_in,
                              void* d_out, int out_size)
{
    const float* F  = (const float*)d_in[0];
    const float* Wg = (const float*)d_in[1];
    if (n_in >= 2 && in_sizes[0] < in_sizes[1]) {
        F  = (const float*)d_in[1];
        Wg = (const float*)d_in[0];
    }

    unsigned long long* keys_a = nullptr;
    unsigned long long* keys_b = nullptr;
    int* offsets = nullptr;
    unsigned char* temp = nullptr;
    cudaGetSymbolAddress((void**)&keys_a,  g_keys_a);
    cudaGetSymbolAddress((void**)&keys_b,  g_keys_b);
    cudaGetSymbolAddress((void**)&offsets, g_offsets);
    cudaGetSymbolAddress((void**)&temp,    g_temp);

    if (out_size == N_TOK) {
        pack_ones<<<(N_TOK + 255) / 256, 256>>>((float*)d_out, N_TOK);
        return;
    }
    if (out_size == 2 * E || out_size == E) {
        pack_splits<<<1, 256>>>((float*)d_out, out_size);
        return;
    }

    gemm_affin<<<N_TOK / 128, 256>>>(F, Wg, keys_a, offsets);

    cub::DoubleBuffer<unsigned long long> dbuf(keys_a, keys_b);
    size_t temp_bytes = 0;
    cub::DeviceRadixSort::SortKeysDescending(
        nullptr, temp_bytes, dbuf, TOTAL, 16, 54);
    if (temp_bytes <= (size_t)(8u << 20)) {
        cub::DeviceRadixSort::SortKeysDescending(
            (void*)temp, temp_bytes, dbuf, TOTAL, 16, 54);
    } else {
        size_t tb2 = 0;
        cub::DeviceSegmentedRadixSort::SortKeysDescending(
            nullptr, tb2, dbuf, TOTAL, E, offsets, offsets + 1, 16, 48);
        if (tb2 > (size_t)(8u << 20)) tb2 = (size_t)(8u << 20);
        cub::DeviceSegmentedRadixSort::SortKeysDescending(
            (void*)temp, tb2, dbuf, TOTAL, E, offsets, offsets + 1, 16, 48);
    }

    greedy_select<<<1, 1024>>>(dbuf.Current(), (float*)d_out, out_size);
}

// round 13
// speedup vs baseline: 1.1585x; 1.0303x over previous
#include <cuda_runtime.h>
#include <cuda_bf16.h>
#include <cub/cub.cuh>
#include <cstdint>

// ---------------------------------------------------------------------------
// BaseLayerGate: affin = F[65536,1024] @ Wg[64,1024]^T ; greedy balanced
// assignment; outputs sbe[65536], splits[64]=1024 (x2), probs[65536]=1.0.
//
// Key: (63-e)<<48 | sortable(score)<<16 | token. ONE global descending radix
// sort over bits [16,54). Stability => ascending-token ties (jax top_k).
// After the sort, tokens are COMPRESSED to u16 into the idle alternate sort
// buffer so the single-CTA greedy kernel is no longer LSU-bound on 8B keys.
// ---------------------------------------------------------------------------

static constexpr int N_TOK = 65536;
static constexpr int D     = 1024;
static constexpr int E     = 64;
static constexpr int C     = N_TOK / E;   // 1024
static constexpr int TOTAL = N_TOK * E;   // 4M

__device__ unsigned long long g_keys_a[TOTAL];    // 32 MB
__device__ unsigned long long g_keys_b[TOTAL];    // 32 MB
__device__ int                g_offsets[E + 1];
__device__ unsigned char      g_temp[8u << 20];   // 8 MB CUB temp

__device__ __forceinline__ unsigned sortable_u(unsigned u) {
    return u ^ ((u & 0x80000000u) ? 0xFFFFFFFFu : 0x80000000u);
}
__device__ __forceinline__ unsigned long long ffma2(
    unsigned long long a, unsigned long long b, unsigned long long c) {
    unsigned long long d;
    asm("fma.rn.f32x2 %0, %1, %2, %3;" : "=l"(d) : "l"(a), "l"(b), "l"(c));
    return d;
}
__device__ __forceinline__ unsigned long long bcast2(float f) {
    unsigned long long p;
    asm("mov.b64 %0, {%1, %1};" : "=l"(p) : "f"(f));
    return p;
}

// ---------------------------------------------------------------------------
// GEMM: exact R6 configuration (the only measured-fast one; R10's variant
// cut occupancy and regressed). f32x2 dual-pumped FFMA, bit-exact chain.
// ---------------------------------------------------------------------------
__global__ __launch_bounds__(256) void gemm_affin(
    const float* __restrict__ F, const float* __restrict__ W,
    unsigned long long* __restrict__ keys, int* __restrict__ offsets)
{
    __shared__ float As[128][33];
    __shared__ float Wst[32][66];   // [kk][expert]
    const int tid  = threadIdx.x;
    const int tile = blockIdx.x * 128;
    const int tx   = tid & 15;
    const int ty   = tid >> 4;

    if (blockIdx.x == 0 && tid <= E) offsets[tid] = tid * N_TOK;

    unsigned long long accp[8][2];
    #pragma unroll
    for (int i = 0; i < 8; ++i) { accp[i][0] = 0ull; accp[i][1] = 0ull; }

    for (int k0 = 0; k0 < D; k0 += 32) {
        #pragma unroll
        for (int it = 0; it < 4; ++it) {
            int idx = tid + it * 256;
            int row = idx >> 3, c4 = idx & 7;
            float4 v = *(const float4*)(F + (size_t)(tile + row) * D + k0 + c4 * 4);
            As[row][c4 * 4 + 0] = v.x; As[row][c4 * 4 + 1] = v.y;
            As[row][c4 * 4 + 2] = v.z; As[row][c4 * 4 + 3] = v.w;
        }
        #pragma unroll
        for (int it = 0; it < 2; ++it) {
            int idx = tid + it * 256;
            int row = idx >> 3, c4 = idx & 7;   // row = expert
            float4 v = *(const float4*)(W + (size_t)row * D + k0 + c4 * 4);
            Wst[c4 * 4 + 0][row] = v.x; Wst[c4 * 4 + 1][row] = v.y;
            Wst[c4 * 4 + 2][row] = v.z; Wst[c4 * 4 + 3][row] = v.w;
        }
        __syncthreads();
        #pragma unroll
        for (int kk = 0; kk < 32; ++kk) {
            unsigned long long wp0 = *(const unsigned long long*)&Wst[kk][tx * 4];
            unsigned long long wp1 = *(const unsigned long long*)&Wst[kk][tx * 4 + 2];
            #pragma unroll
            for (int i = 0; i < 8; ++i) {
                unsigned long long fp = bcast2(As[ty * 8 + i][kk]);
                accp[i][0] = ffma2(fp, wp0, accp[i][0]);
                accp[i][1] = ffma2(fp, wp1, accp[i][1]);
            }
        }
        __syncthreads();
    }
    #pragma unroll
    for (int i = 0; i < 8; ++i) {
        unsigned t = (unsigned)(tile + ty * 8 + i);
        #pragma unroll
        for (int jp = 0; jp < 2; ++jp) {
            unsigned lo, hi;
            asm("mov.b64 {%0, %1}, %2;" : "=r"(lo), "=r"(hi) : "l"(accp[i][jp]));
            int e0 = tx * 4 + 2 * jp;
            unsigned long long k0 =
                ((unsigned long long)(63 - e0) << 48) |
                ((unsigned long long)sortable_u(lo) << 16) | t;
            unsigned long long k1 =
                ((unsigned long long)(63 - (e0 + 1)) << 48) |
                ((unsigned long long)sortable_u(hi) << 16) | t;
            keys[(size_t)e0 * N_TOK + t]       = k0;
            keys[(size_t)(e0 + 1) * N_TOK + t] = k1;
        }
    }
}

// ---------------------------------------------------------------------------
// Token compression: sorted u64 keys -> u16 token stream (full chip,
// bandwidth-bound: 32MB read + 8MB write). Each thread: 4 keys -> 1 STG.64.
// ---------------------------------------------------------------------------
__global__ __launch_bounds__(256) void extract_tokens(
    const unsigned long long* __restrict__ keys,
    unsigned short* __restrict__ toks)
{
    int idx = blockIdx.x * blockDim.x + threadIdx.x;   // one per 4 keys
    ulonglong2 a = *(const ulonglong2*)(keys + (size_t)idx * 4);
    ulonglong2 b = *(const ulonglong2*)(keys + (size_t)idx * 4 + 2);
    uint2 packed;
    packed.x = ((unsigned)a.x & 0xFFFFu) | (((unsigned)a.y & 0xFFFFu) << 16);
    packed.y = ((unsigned)b.x & 0xFFFFu) | (((unsigned)b.y & 0xFFFFu) << 16);
    *(uint2*)(toks + (size_t)idx * 4) = packed;
}

// ---------------------------------------------------------------------------
// Greedy: single CTA, 1024 threads x 8 u16 tokens per window (8192/window,
// one LDG.128 per thread -> 8x fewer LSU issues than the u64-key version,
// which was single-SM LSU-bound at ~2.3us/window). 2-barrier block scan.
// Writes float(token) directly to d_out; fills constant tail at startup.
// ---------------------------------------------------------------------------
__global__ __launch_bounds__(1024) void greedy_select(
    const unsigned short* __restrict__ toks, float* __restrict__ out,
    int out_size)
{
    __shared__ unsigned mask[N_TOK / 32];  // 8 KB
    __shared__ int warp_sums[32];
    const int tid  = threadIdx.x;
    const int lane = tid & 31;
    const int wid  = tid >> 5;

    for (int i = N_TOK + tid; i < out_size; i += 1024)
        out[i] = (i < N_TOK + 2 * E) ? (float)C : 1.0f;

    for (int i = tid; i < N_TOK / 32; i += 1024) mask[i] = 0u;
    __syncthreads();

    for (int e = 0; e < E; ++e) {
        const unsigned short* ord = toks + (size_t)e * N_TOK;
        int count = 0, pos = 0;
        while (count < C && pos < N_TOK) {
            uint4 w = *(const uint4*)(ord + pos + tid * 8);
            unsigned tk[8];
            tk[0] = w.x & 0xFFFFu; tk[1] = w.x >> 16;
            tk[2] = w.y & 0xFFFFu; tk[3] = w.y >> 16;
            tk[4] = w.z & 0xFFFFu; tk[5] = w.z >> 16;
            tk[6] = w.w & 0xFFFFu; tk[7] = w.w >> 16;
            int fl[8], cnt = 0;
            #pragma unroll
            for (int j = 0; j < 8; ++j) {
                fl[j] = 1 - (int)((mask[tk[j] >> 5] >> (tk[j] & 31)) & 1u);
                cnt += fl[j];
            }
            int inc = cnt;
            #pragma unroll
            for (int off = 1; off < 32; off <<= 1) {
                int n = __shfl_up_sync(0xffffffffu, inc, off);
                if (lane >= off) inc += n;
            }
            if (lane == 31) warp_sums[wid] = inc;
            int thr_excl = inc - cnt;
            __syncthreads();
            // every warp redundantly scans the 32 warp sums (one barrier saved)
            int v = warp_sums[lane];
            #pragma unroll
            for (int off = 1; off < 32; off <<= 1) {
                int n = __shfl_up_sync(0xffffffffu, v, off);
                if (lane >= off) v += n;
            }
            int total     = __shfl_sync(0xffffffffu, v, 31);
            int warp_excl = wid ? __shfl_sync(0xffffffffu, v, wid - 1) : 0;
            int remaining = C - count;
            int r = warp_excl + thr_excl;
            #pragma unroll
            for (int j = 0; j < 8; ++j) {
                if (fl[j]) {
                    if (r < remaining) {
                        out[e * C + count + r] = (float)tk[j];
                        atomicOr(&mask[tk[j] >> 5], 1u << (tk[j] & 31));
                    }
                    ++r;
                }
            }
            count += min(total, remaining);
            pos += 8192;
            __syncthreads();
        }
    }
}

// ---------------------------------------------------------------------------
__global__ void pack_ones(float* __restrict__ out, int n)
{
    int i = blockIdx.x * blockDim.x + threadIdx.x;
    if (i < n) out[i] = 1.0f;
}

__global__ void pack_splits(float* __restrict__ out, int n)
{
    int i = blockIdx.x * blockDim.x + threadIdx.x;
    if (i < n) out[i] = (float)C;
}

// ---------------------------------------------------------------------------
extern "C" void kernel_launch(void* const* d_in, const int* in_sizes, int n_in,
                              void* d_out, int out_size)
{
    const float* F  = (const float*)d_in[0];
    const float* Wg = (const float*)d_in[1];
    if (n_in >= 2 && in_sizes[0] < in_sizes[1]) {
        F  = (const float*)d_in[1];
        Wg = (const float*)d_in[0];
    }

    unsigned long long* keys_a = nullptr;
    unsigned long long* keys_b = nullptr;
    int* offsets = nullptr;
    unsigned char* temp = nullptr;
    cudaGetSymbolAddress((void**)&keys_a,  g_keys_a);
    cudaGetSymbolAddress((void**)&keys_b,  g_keys_b);
    cudaGetSymbolAddress((void**)&offsets, g_offsets);
    cudaGetSymbolAddress((void**)&temp,    g_temp);

    if (out_size == N_TOK) {
        pack_ones<<<(N_TOK + 255) / 256, 256>>>((float*)d_out, N_TOK);
        return;
    }
    if (out_size == 2 * E || out_size == E) {
        pack_splits<<<1, 256>>>((float*)d_out, out_size);
        return;
    }

    gemm_affin<<<N_TOK / 128, 256>>>(F, Wg, keys_a, offsets);

    cub::DoubleBuffer<unsigned long long> dbuf(keys_a, keys_b);
    size_t temp_bytes = 0;
    cub::DeviceRadixSort::SortKeysDescending(
        nullptr, temp_bytes, dbuf, TOTAL, 16, 54);
    if (temp_bytes <= (size_t)(8u << 20)) {
        cub::DeviceRadixSort::SortKeysDescending(
            (void*)temp, temp_bytes, dbuf, TOTAL, 16, 54);
    } else {
        size_t tb2 = 0;
        cub::DeviceSegmentedRadixSort::SortKeysDescending(
            nullptr, tb2, dbuf, TOTAL, E, offsets, offsets + 1, 16, 48);
        if (tb2 > (size_t)(8u << 20)) tb2 = (size_t)(8u << 20);
        cub::DeviceSegmentedRadixSort::SortKeysDescending(
            (void*)temp, tb2, dbuf, TOTAL, E, offsets, offsets + 1, 16, 48);
    }

    // Compress tokens into the idle alternate sort buffer (no new memory).
    unsigned short* toks = (unsigned short*)dbuf.Alternate();
    extract_tokens<<<TOTAL / 4 / 256, 256>>>(dbuf.Current(), toks);

    greedy_select<<<1, 1024>>>(toks, (float*)d_out, out_size);
}